// round 14
// baseline (speedup 1.0000x reference)
#include <cuda_runtime.h>
#include <cuda_bf16.h>
#include <cuda_fp16.h>
#include <cstdint>

// Problem constants
#define NN   50000
#define EE   800000
#define FIN  128
#define FHID 128
#define FOUT 64
#define SLOTS 64   // max in-degree slots per node (Poisson(16): P(deg>=64) ~ 1e-20)

// ---------------------------------------------------------------------------
// Scratch (static __device__ arrays — no allocation allowed)
// ---------------------------------------------------------------------------
__device__ __half  g_h1[(size_t)NN * FHID];  // GEMM1 out: x@W1 (UNSCALED, fp16)
__device__ __half  g_hh[(size_t)NN * FHID];  // h = relu(dis*sum + b1), fp16
__device__ __half  g_h2[(size_t)NN * FOUT];  // GEMM2 out: h@W2 (UNSCALED, fp16)
__device__ int     g_cnt[NN];                // per-node edge count (atomic)
__device__ __half2 g_dish[NN];               // dis as half2 (duplicated lanes)
__device__ int     g_slots[(size_t)NN * SLOTS]; // direct-mapped CSR
__device__ __half  g_w1h[FIN * FHID];
__device__ __half  g_w2h[FHID * FOUT];

// ---------------------------------------------------------------------------
// PTX helpers
// ---------------------------------------------------------------------------
__device__ __forceinline__ uint32_t smem_u32(const void* p) {
    return (uint32_t)__cvta_generic_to_shared(p);
}

__device__ __forceinline__ void ldmat_x4(uint32_t& r0, uint32_t& r1, uint32_t& r2, uint32_t& r3,
                                         uint32_t addr) {
    asm volatile("ldmatrix.sync.aligned.m8n8.x4.shared.b16 {%0,%1,%2,%3}, [%4];"
                 : "=r"(r0), "=r"(r1), "=r"(r2), "=r"(r3) : "r"(addr));
}
__device__ __forceinline__ void ldmat_x4_t(uint32_t& r0, uint32_t& r1, uint32_t& r2, uint32_t& r3,
                                           uint32_t addr) {
    asm volatile("ldmatrix.sync.aligned.m8n8.x4.trans.shared.b16 {%0,%1,%2,%3}, [%4];"
                 : "=r"(r0), "=r"(r1), "=r"(r2), "=r"(r3) : "r"(addr));
}

__device__ __forceinline__ void mma_f16(float* d, const uint32_t* a, uint32_t b0, uint32_t b1) {
    asm volatile(
        "mma.sync.aligned.m16n8k16.row.col.f32.f16.f16.f32 "
        "{%0,%1,%2,%3}, {%4,%5,%6,%7}, {%8,%9}, {%0,%1,%2,%3};"
        : "+f"(d[0]), "+f"(d[1]), "+f"(d[2]), "+f"(d[3])
        : "r"(a[0]), "r"(a[1]), "r"(a[2]), "r"(a[3]), "r"(b0), "r"(b1));
}

// a[j] += v[j] * s  (fp16x2 FMA, same op count as plain HADD2 accumulate)
__device__ __forceinline__ void hfma4(__half2* a, uint4 raw, __half2 s) {
    const __half2* h = (const __half2*)&raw;
    a[0] = __hfma2(h[0], s, a[0]);
    a[1] = __hfma2(h[1], s, a[1]);
    a[2] = __hfma2(h[2], s, a[2]);
    a[3] = __hfma2(h[3], s, a[3]);
}

// ---------------------------------------------------------------------------
// One-shot W conversion fp32 -> fp16
// ---------------------------------------------------------------------------
__global__ void wconv_kernel(const float* __restrict__ W1, const float* __restrict__ W2,
                             __half* __restrict__ w1h, __half* __restrict__ w2h) {
    constexpr int N1 = (FIN * FHID) / 2;
    constexpr int N2 = (FHID * FOUT) / 2;
    int i = blockIdx.x * blockDim.x + threadIdx.x;
    if (i < N1) {
        float2 v = *(const float2*)(W1 + (size_t)i * 2);
        *(__half2*)(w1h + (size_t)i * 2) = __floats2half2_rn(v.x, v.y);
    } else if (i < N1 + N2) {
        int j = i - N1;
        float2 v = *(const float2*)(W2 + (size_t)j * 2);
        *(__half2*)(w2h + (size_t)j * 2) = __floats2half2_rn(v.x, v.y);
    }
}

// ---------------------------------------------------------------------------
// Single-pass CSR build: slot = cnt[col]++; slots[col*SLOTS + slot] = row
// ---------------------------------------------------------------------------
__global__ void fill_direct_kernel(const int* __restrict__ row, const int* __restrict__ col,
                                   int* __restrict__ cnt, int* __restrict__ slots, int e) {
    int i = blockIdx.x * blockDim.x + threadIdx.x;
    if (i < e) {
        int c = col[i];
        int s = atomicAdd(&cnt[c], 1);
        slots[(size_t)c * SLOTS + s] = row[i];
    }
}

// dis table: dish[i] = half2(rsqrt(cnt[i]+1)) duplicated in both lanes
__global__ void dish_kernel(const int* __restrict__ cnt, __half2* __restrict__ dish, int n) {
    int i = blockIdx.x * blockDim.x + threadIdx.x;
    if (i < n) {
        float d = rsqrtf((float)cnt[i] + 1.0f);
        dish[i] = __floats2half2_rn(d, d);
    }
}

// ---------------------------------------------------------------------------
// Tensor-core GEMM, fp16 inputs, FULL K (=128) in smem, 1 barrier:
//   out[N, F] = x[N, 128] @ W[128, F]   (PURE — no graph dependency)
// BM=64, 8 warps (warp = 16-row slab x F/2 cols).
// ---------------------------------------------------------------------------
template <int F, typename TIN>
__global__ void __launch_bounds__(256)
gemm_tc_kernel(const TIN* __restrict__ x,
               const __half* __restrict__ wg,
               __half* __restrict__ out, int nrows) {
    constexpr int BM   = 64;
    constexpr int KT   = 128;
    constexpr int NT   = F / 16;
    constexpr int ASTR = KT + 8;
    constexpr int WSTR = F + 8;

    extern __shared__ __half smem[];
    __half* Ah = smem;
    __half* Wh = Ah + BM * ASTR;

    const int tid  = threadIdx.x;
    const int lane = tid & 31;
    const int w    = tid >> 5;
    const int slab = w >> 1;
    const int ch   = w & 1;
    const int row0 = blockIdx.x * BM;

    float acc[NT][4];
#pragma unroll
    for (int nt = 0; nt < NT; nt++)
#pragma unroll
        for (int j = 0; j < 4; j++) acc[nt][j] = 0.f;

    const int mat  = lane >> 3;
    const int mrow = lane & 7;

    if constexpr (sizeof(TIN) == 4) {
        constexpr int NV = (BM * KT) / 4;
#pragma unroll
        for (int p = tid; p < NV; p += 256) {
            int r  = p / (KT / 4);
            int kq = (p % (KT / 4)) * 4;
            float4 v;
            int grow = row0 + r;
            if (grow < nrows)
                v = *(const float4*)((const float*)x + (size_t)grow * FIN + kq);
            else
                v = make_float4(0.f, 0.f, 0.f, 0.f);
            *(__half2*)(Ah + r * ASTR + kq)     = __floats2half2_rn(v.x, v.y);
            *(__half2*)(Ah + r * ASTR + kq + 2) = __floats2half2_rn(v.z, v.w);
        }
    } else {
        constexpr int NV = (BM * KT) / 8;
#pragma unroll
        for (int p = tid; p < NV; p += 256) {
            int r  = p / (KT / 8);
            int kq = (p % (KT / 8)) * 8;
            uint4 v;
            int grow = row0 + r;
            if (grow < nrows)
                v = *(const uint4*)((const __half*)x + (size_t)grow * FIN + kq);
            else
                v = make_uint4(0, 0, 0, 0);
            *(uint4*)(Ah + r * ASTR + kq) = v;
        }
    }
    {
        constexpr int NV = (KT * F) / 8;
#pragma unroll
        for (int p = tid; p < NV; p += 256) {
            int k = p / (F / 8);
            int c = (p % (F / 8)) * 8;
            *(uint4*)(Wh + k * WSTR + c) = *(const uint4*)(wg + (size_t)k * F + c);
        }
    }
    __syncthreads();

#pragma unroll
    for (int ks = 0; ks < KT / 16; ks++) {
        uint32_t ah[4];
        {
            int arow = slab * 16 + (mat & 1) * 8 + mrow;
            int acol = ks * 16 + (mat >> 1) * 8;
            ldmat_x4(ah[0], ah[1], ah[2], ah[3], smem_u32(Ah + arow * ASTR + acol));
        }
#pragma unroll
        for (int nt2 = 0; nt2 < NT / 2; nt2++) {
            int krow = ks * 16 + (mat & 1) * 8 + mrow;
            int ncol = ch * (F / 2) + nt2 * 16 + (mat >> 1) * 8;
            uint32_t bh[4];
            ldmat_x4_t(bh[0], bh[1], bh[2], bh[3], smem_u32(Wh + krow * WSTR + ncol));
            mma_f16(acc[2 * nt2],     ah, bh[0], bh[1]);
            mma_f16(acc[2 * nt2 + 1], ah, bh[2], bh[3]);
        }
    }

    {
        int r0 = row0 + slab * 16 + (lane >> 2);
        int r1 = r0 + 8;
        int cbase = ch * (F / 2) + (lane & 3) * 2;
#pragma unroll
        for (int nt = 0; nt < NT; nt++) {
            int c = cbase + nt * 8;
            if (r0 < nrows)
                *(__half2*)(out + (size_t)r0 * F + c) = __floats2half2_rn(acc[nt][0], acc[nt][1]);
            if (r1 < nrows)
                *(__half2*)(out + (size_t)r1 * F + c) = __floats2half2_rn(acc[nt][2], acc[nt][3]);
        }
    }
}

// ---------------------------------------------------------------------------
// Segment-sum aggregate over fp16 features with per-edge dis scale (HFMA2):
//   out[c] = act( dis[c] * ( dis[c]*h[c] + sum_e dis[r]*h[r] ) + bias )
// dis comes from the precomputed half2 table; fp32 final combine.
// ---------------------------------------------------------------------------
template <int F, bool RELU, typename TOUT>
__global__ void __launch_bounds__(256)
aggregate_kernel(const __half* __restrict__ hs,
                 const int* __restrict__ slots, const int* __restrict__ cnt,
                 const __half2* __restrict__ dish,
                 const float* __restrict__ bias,
                 TOUT* __restrict__ out, int n) {
    constexpr int LPN = F / 8;
    const int gtid = blockIdx.x * blockDim.x + threadIdx.x;
    const int node = gtid / LPN;
    const int sub  = gtid % LPN;
    if (node >= n) return;

    const int deg = __ldg(cnt + node);
    const int beg = node * SLOTS;
    const int end = beg + deg;

    const __half2 dself = __ldg(dish + node);

    __half2 a0[4], a1[4], a2[4], a3[4];
    // self loop seeds a0 = dis[node] * h[node]
    {
        uint4 s = *(const uint4*)(hs + (size_t)node * F + sub * 8);
        const __half2* h = (const __half2*)&s;
        __half2 z = __floats2half2_rn(0.f, 0.f);
#pragma unroll
        for (int j = 0; j < 4; j++) { a0[j] = __hmul2(h[j], dself); a1[j] = z; a2[j] = z; a3[j] = z; }
    }

    int e = beg;
    for (; e + 3 < end; e += 4) {
        int r0 = __ldg(slots + e);
        int r1 = __ldg(slots + e + 1);
        int r2 = __ldg(slots + e + 2);
        int r3 = __ldg(slots + e + 3);
        __half2 d0 = __ldg(dish + r0);
        __half2 d1 = __ldg(dish + r1);
        __half2 d2 = __ldg(dish + r2);
        __half2 d3 = __ldg(dish + r3);
        uint4 v0 = *(const uint4*)(hs + (size_t)r0 * F + sub * 8);
        uint4 v1 = *(const uint4*)(hs + (size_t)r1 * F + sub * 8);
        uint4 v2 = *(const uint4*)(hs + (size_t)r2 * F + sub * 8);
        uint4 v3 = *(const uint4*)(hs + (size_t)r3 * F + sub * 8);
        hfma4(a0, v0, d0); hfma4(a1, v1, d1); hfma4(a2, v2, d2); hfma4(a3, v3, d3);
    }
    for (; e < end; e++) {
        int r0 = __ldg(slots + e);
        __half2 d0 = __ldg(dish + r0);
        hfma4(a1, *(const uint4*)(hs + (size_t)r0 * F + sub * 8), d0);
    }

    // fp32 final combine + dis[node] scale + bias
    const float d = rsqrtf((float)deg + 1.0f);
    float4 bva = *(const float4*)(bias + sub * 8);
    float4 bvb = *(const float4*)(bias + sub * 8 + 4);
    float o[8];
#pragma unroll
    for (int j = 0; j < 4; j++) {
        float2 f0 = __half22float2(a0[j]);
        float2 f1 = __half22float2(a1[j]);
        float2 f2 = __half22float2(a2[j]);
        float2 f3 = __half22float2(a3[j]);
        o[2 * j]     = (f0.x + f1.x) + (f2.x + f3.x);
        o[2 * j + 1] = (f0.y + f1.y) + (f2.y + f3.y);
    }
#pragma unroll
    for (int j = 0; j < 8; j++) {
        float bj = (j < 4) ? ((const float*)&bva)[j] : ((const float*)&bvb)[j - 4];
        o[j] = o[j] * d + bj;
        if (RELU) o[j] = fmaxf(o[j], 0.f);
    }

    if constexpr (sizeof(TOUT) == 2) {
        __half2 p[4];
#pragma unroll
        for (int j = 0; j < 4; j++) p[j] = __floats2half2_rn(o[2 * j], o[2 * j + 1]);
        *(uint4*)((__half*)out + (size_t)node * F + sub * 8) = *(uint4*)p;
    } else {
        float* op = (float*)out + (size_t)node * F + sub * 8;
        *(float4*)(op)     = make_float4(o[0], o[1], o[2], o[3]);
        *(float4*)(op + 4) = make_float4(o[4], o[5], o[6], o[7]);
    }
}

// ---------------------------------------------------------------------------
// Launch: side stream = memset + fill + dis table (graph build),
//         main stream = wconv + GEMM1 (pure GEMM — NO graph dependency).
//         Join only before aggregate1.
// ---------------------------------------------------------------------------
extern "C" void kernel_launch(void* const* d_in, const int* in_sizes, int n_in,
                              void* d_out, int out_size) {
    const float* x  = (const float*)d_in[0];
    const int*   ei = (const int*)d_in[1];
    const float* W1 = (const float*)d_in[2];
    const float* b1 = (const float*)d_in[3];
    const float* W2 = (const float*)d_in[4];
    const float* b2 = (const float*)d_in[5];
    float* out = (float*)d_out;

    const int* row = ei;
    const int* col = ei + EE;

    constexpr int SMEM1 = (64 * 136 + 128 * 136) * 2;  // 52,224 B (F=128)
    constexpr int SMEM2 = (64 * 136 + 128 * 72) * 2;   // 35,840 B (F=64)

    static __half *p_h1 = nullptr, *p_hh = nullptr, *p_h2 = nullptr,
                  *p_w1h = nullptr, *p_w2h = nullptr;
    static __half2 *p_dish = nullptr;
    static int *p_cnt = nullptr, *p_slots = nullptr;
    static cudaStream_t s_side = nullptr;
    static cudaEvent_t s_fork = nullptr, s_join = nullptr;
    if (!p_h1) {
        cudaGetSymbolAddress((void**)&p_h1,    g_h1);
        cudaGetSymbolAddress((void**)&p_hh,    g_hh);
        cudaGetSymbolAddress((void**)&p_h2,    g_h2);
        cudaGetSymbolAddress((void**)&p_cnt,   g_cnt);
        cudaGetSymbolAddress((void**)&p_dish,  g_dish);
        cudaGetSymbolAddress((void**)&p_slots, g_slots);
        cudaGetSymbolAddress((void**)&p_w1h,   g_w1h);
        cudaGetSymbolAddress((void**)&p_w2h,   g_w2h);
        cudaFuncSetAttribute((const void*)gemm_tc_kernel<128, float>,
                             cudaFuncAttributeMaxDynamicSharedMemorySize, SMEM1);
        cudaFuncSetAttribute((const void*)gemm_tc_kernel<64, __half>,
                             cudaFuncAttributeMaxDynamicSharedMemorySize, SMEM2);
        cudaStreamCreateWithFlags(&s_side, cudaStreamNonBlocking);
        cudaEventCreateWithFlags(&s_fork, cudaEventDisableTiming);
        cudaEventCreateWithFlags(&s_join, cudaEventDisableTiming);
    }

    const int GBLK = (NN + 63) / 64;       // 782

    // ---- fork: CSR build + dis table on side stream ----
    cudaEventRecord(s_fork, 0);
    cudaStreamWaitEvent(s_side, s_fork, 0);
    cudaMemsetAsync(p_cnt, 0, (size_t)NN * sizeof(int), s_side);
    fill_direct_kernel<<<(EE + 255) / 256, 256, 0, s_side>>>(row, col, p_cnt, p_slots, EE);
    dish_kernel<<<(NN + 255) / 256, 256, 0, s_side>>>(p_cnt, p_dish, NN);
    cudaEventRecord(s_join, s_side);

    // ---- main: W conversion + layer 1 GEMM (pure, fully overlapped) ----
    {
        constexpr int NPAIR = (FIN * FHID + FHID * FOUT) / 2;
        wconv_kernel<<<(NPAIR + 255) / 256, 256>>>(W1, W2, p_w1h, p_w2h);
    }
    gemm_tc_kernel<128, float><<<GBLK, 256, SMEM1>>>(x, p_w1h, p_h1, NN);

    // ---- join: aggregate needs CSR + dis ----
    cudaStreamWaitEvent(0, s_join, 0);

    // ---- layer 1 aggregate -> h (fp16) ----
    {
        long long threads = (long long)NN * (FHID / 8);
        aggregate_kernel<128, true, __half><<<(int)((threads + 255) / 256), 256>>>(
            p_h1, p_slots, p_cnt, p_dish, b1, p_hh, NN);
    }

    // ---- layer 2: fp16 tensor GEMM (pure) ----
    gemm_tc_kernel<64, __half><<<GBLK, 256, SMEM2>>>(p_hh, p_w2h, p_h2, NN);

    // ---- layer 2 aggregate -> d_out (fp32) ----
    {
        long long threads = (long long)NN * (FOUT / 8);
        aggregate_kernel<64, false, float><<<(int)((threads + 255) / 256), 256>>>(
            p_h2, p_slots, p_cnt, p_dish, b2, out, NN);
    }
}

// round 15
// speedup vs baseline: 1.1887x; 1.1887x over previous
#include <cuda_runtime.h>
#include <cuda_bf16.h>
#include <cuda_fp16.h>
#include <cstdint>

// Problem constants
#define NN   50000
#define EE   800000
#define FIN  128
#define FHID 128
#define FOUT 64
#define SLOTS 64   // max in-degree slots per node (Poisson(16): P(deg>=64) ~ 1e-20)

// ---------------------------------------------------------------------------
// Scratch (static __device__ arrays — no allocation allowed)
// ---------------------------------------------------------------------------
__device__ __half g_hs1[(size_t)NN * FHID];  // GEMM1 out: (x@W1)*dis, fp16
__device__ __half g_hh[(size_t)NN * FHID];   // h = relu(dis*sum + b1),  fp16
__device__ __half g_hs2[(size_t)NN * FOUT];  // GEMM2 out: (h@W2)*dis,  fp16
__device__ int    g_cnt[NN];                 // per-node edge count (atomic)
__device__ int    g_slots[(size_t)NN * SLOTS]; // direct-mapped CSR (64-aligned rows)
__device__ __half g_w1h[FIN * FHID];
__device__ __half g_w2h[FHID * FOUT];

// ---------------------------------------------------------------------------
// PTX helpers
// ---------------------------------------------------------------------------
__device__ __forceinline__ uint32_t smem_u32(const void* p) {
    return (uint32_t)__cvta_generic_to_shared(p);
}

__device__ __forceinline__ void ldmat_x4(uint32_t& r0, uint32_t& r1, uint32_t& r2, uint32_t& r3,
                                         uint32_t addr) {
    asm volatile("ldmatrix.sync.aligned.m8n8.x4.shared.b16 {%0,%1,%2,%3}, [%4];"
                 : "=r"(r0), "=r"(r1), "=r"(r2), "=r"(r3) : "r"(addr));
}
__device__ __forceinline__ void ldmat_x4_t(uint32_t& r0, uint32_t& r1, uint32_t& r2, uint32_t& r3,
                                           uint32_t addr) {
    asm volatile("ldmatrix.sync.aligned.m8n8.x4.trans.shared.b16 {%0,%1,%2,%3}, [%4];"
                 : "=r"(r0), "=r"(r1), "=r"(r2), "=r"(r3) : "r"(addr));
}

__device__ __forceinline__ void mma_f16(float* d, const uint32_t* a, uint32_t b0, uint32_t b1) {
    asm volatile(
        "mma.sync.aligned.m16n8k16.row.col.f32.f16.f16.f32 "
        "{%0,%1,%2,%3}, {%4,%5,%6,%7}, {%8,%9}, {%0,%1,%2,%3};"
        : "+f"(d[0]), "+f"(d[1]), "+f"(d[2]), "+f"(d[3])
        : "r"(a[0]), "r"(a[1]), "r"(a[2]), "r"(a[3]), "r"(b0), "r"(b1));
}

// fp16x2 accumulate of one uint4 (8 halves) into 4 half2 accumulators
__device__ __forceinline__ void hacc4(__half2* a, uint4 raw) {
    const __half2* h = (const __half2*)&raw;
    a[0] = __hadd2(a[0], h[0]);
    a[1] = __hadd2(a[1], h[1]);
    a[2] = __hadd2(a[2], h[2]);
    a[3] = __hadd2(a[3], h[3]);
}

// ---------------------------------------------------------------------------
// One-shot W conversion fp32 -> fp16
// ---------------------------------------------------------------------------
__global__ void wconv_kernel(const float* __restrict__ W1, const float* __restrict__ W2,
                             __half* __restrict__ w1h, __half* __restrict__ w2h) {
    constexpr int N1 = (FIN * FHID) / 2;
    constexpr int N2 = (FHID * FOUT) / 2;
    int i = blockIdx.x * blockDim.x + threadIdx.x;
    if (i < N1) {
        float2 v = *(const float2*)(W1 + (size_t)i * 2);
        *(__half2*)(w1h + (size_t)i * 2) = __floats2half2_rn(v.x, v.y);
    } else if (i < N1 + N2) {
        int j = i - N1;
        float2 v = *(const float2*)(W2 + (size_t)j * 2);
        *(__half2*)(w2h + (size_t)j * 2) = __floats2half2_rn(v.x, v.y);
    }
}

// ---------------------------------------------------------------------------
// Single-pass CSR build, 2 edges/thread (2 independent atomic+store chains;
// 400k threads keeps the chip oversubscribed, unlike the failed 4-edge variant)
// ---------------------------------------------------------------------------
__global__ void fill_direct_kernel(const int* __restrict__ row, const int* __restrict__ col,
                                   int* __restrict__ cnt, int* __restrict__ slots, int e) {
    int i = blockIdx.x * blockDim.x + threadIdx.x;
    int j = i * 2;
    if (j + 1 < e) {
        int2 c = *(const int2*)(col + j);
        int2 r = *(const int2*)(row + j);
        int s0 = atomicAdd(&cnt[c.x], 1);
        int s1 = atomicAdd(&cnt[c.y], 1);
        slots[(size_t)c.x * SLOTS + s0] = r.x;
        slots[(size_t)c.y * SLOTS + s1] = r.y;
    } else if (j < e) {
        int c = col[j];
        int s = atomicAdd(&cnt[c], 1);
        slots[(size_t)c * SLOTS + s] = row[j];
    }
}

// ---------------------------------------------------------------------------
// Tensor-core GEMM, fp16 inputs, FULL K (=128) resident in smem (1 barrier):
//   out[N, F] = (x[N, 128] @ W[128, F]) * rsqrt(cnt[row]+1),  out fp16.
// BM=64, 8 warps (warp = 16-row slab x F/2 cols).
// ---------------------------------------------------------------------------
template <int F, typename TIN>
__global__ void __launch_bounds__(256)
gemm_tc_kernel(const TIN* __restrict__ x,
               const __half* __restrict__ wg,
               __half* __restrict__ out, const int* __restrict__ cnt, int nrows) {
    constexpr int BM   = 64;
    constexpr int KT   = 128;
    constexpr int NT   = F / 16;
    constexpr int ASTR = KT + 8;
    constexpr int WSTR = F + 8;

    extern __shared__ __half smem[];
    __half* Ah = smem;
    __half* Wh = Ah + BM * ASTR;

    const int tid  = threadIdx.x;
    const int lane = tid & 31;
    const int w    = tid >> 5;
    const int slab = w >> 1;
    const int ch   = w & 1;
    const int row0 = blockIdx.x * BM;

    float acc[NT][4];
#pragma unroll
    for (int nt = 0; nt < NT; nt++)
#pragma unroll
        for (int j = 0; j < 4; j++) acc[nt][j] = 0.f;

    const int mat  = lane >> 3;
    const int mrow = lane & 7;

    if constexpr (sizeof(TIN) == 4) {
        constexpr int NV = (BM * KT) / 4;
#pragma unroll
        for (int p = tid; p < NV; p += 256) {
            int r  = p / (KT / 4);
            int kq = (p % (KT / 4)) * 4;
            float4 v;
            int grow = row0 + r;
            if (grow < nrows)
                v = *(const float4*)((const float*)x + (size_t)grow * FIN + kq);
            else
                v = make_float4(0.f, 0.f, 0.f, 0.f);
            *(__half2*)(Ah + r * ASTR + kq)     = __floats2half2_rn(v.x, v.y);
            *(__half2*)(Ah + r * ASTR + kq + 2) = __floats2half2_rn(v.z, v.w);
        }
    } else {
        constexpr int NV = (BM * KT) / 8;
#pragma unroll
        for (int p = tid; p < NV; p += 256) {
            int r  = p / (KT / 8);
            int kq = (p % (KT / 8)) * 8;
            uint4 v;
            int grow = row0 + r;
            if (grow < nrows)
                v = *(const uint4*)((const __half*)x + (size_t)grow * FIN + kq);
            else
                v = make_uint4(0, 0, 0, 0);
            *(uint4*)(Ah + r * ASTR + kq) = v;
        }
    }
    {
        constexpr int NV = (KT * F) / 8;
#pragma unroll
        for (int p = tid; p < NV; p += 256) {
            int k = p / (F / 8);
            int c = (p % (F / 8)) * 8;
            *(uint4*)(Wh + k * WSTR + c) = *(const uint4*)(wg + (size_t)k * F + c);
        }
    }
    __syncthreads();

#pragma unroll
    for (int ks = 0; ks < KT / 16; ks++) {
        uint32_t ah[4];
        {
            int arow = slab * 16 + (mat & 1) * 8 + mrow;
            int acol = ks * 16 + (mat >> 1) * 8;
            ldmat_x4(ah[0], ah[1], ah[2], ah[3], smem_u32(Ah + arow * ASTR + acol));
        }
#pragma unroll
        for (int nt2 = 0; nt2 < NT / 2; nt2++) {
            int krow = ks * 16 + (mat & 1) * 8 + mrow;
            int ncol = ch * (F / 2) + nt2 * 16 + (mat >> 1) * 8;
            uint32_t bh[4];
            ldmat_x4_t(bh[0], bh[1], bh[2], bh[3], smem_u32(Wh + krow * WSTR + ncol));
            mma_f16(acc[2 * nt2],     ah, bh[0], bh[1]);
            mma_f16(acc[2 * nt2 + 1], ah, bh[2], bh[3]);
        }
    }

    {
        int r0 = row0 + slab * 16 + (lane >> 2);
        int r1 = r0 + 8;
        float s0 = (r0 < nrows) ? rsqrtf((float)__ldg(cnt + r0) + 1.0f) : 0.f;
        float s1 = (r1 < nrows) ? rsqrtf((float)__ldg(cnt + r1) + 1.0f) : 0.f;
        int cbase = ch * (F / 2) + (lane & 3) * 2;
#pragma unroll
        for (int nt = 0; nt < NT; nt++) {
            int c = cbase + nt * 8;
            if (r0 < nrows)
                *(__half2*)(out + (size_t)r0 * F + c) = __floats2half2_rn(acc[nt][0] * s0, acc[nt][1] * s0);
            if (r1 < nrows)
                *(__half2*)(out + (size_t)r1 * F + c) = __floats2half2_rn(acc[nt][2] * s1, acc[nt][3] * s1);
        }
    }
}

// ---------------------------------------------------------------------------
// Segment-sum aggregate over fp16 features; HADD2 accumulation, 4-way ILP,
// int4 slot loads (beg is 64-aligned) with software-pipelined prefetch to
// hide the slot-index -> gather dependency. fp32 final combine.
// ---------------------------------------------------------------------------
template <int F, bool RELU, typename TOUT>
__global__ void __launch_bounds__(256)
aggregate_kernel(const __half* __restrict__ hs,
                 const int* __restrict__ slots, const int* __restrict__ cnt,
                 const float* __restrict__ bias,
                 TOUT* __restrict__ out, int n) {
    constexpr int LPN = F / 8;
    const int gtid = blockIdx.x * blockDim.x + threadIdx.x;
    const int node = gtid / LPN;
    const int sub  = gtid % LPN;
    if (node >= n) return;

    const int deg = __ldg(cnt + node);
    const int beg = node * SLOTS;

    __half2 a0[4], a1[4], a2[4], a3[4];
    // self loop seeds a0; others zero
    {
        uint4 s = *(const uint4*)(hs + (size_t)node * F + sub * 8);
        const __half2* h = (const __half2*)&s;
        __half2 z = __floats2half2_rn(0.f, 0.f);
#pragma unroll
        for (int j = 0; j < 4; j++) { a0[j] = h[j]; a1[j] = z; a2[j] = z; a3[j] = z; }
    }

    const int nq = deg >> 2;          // full quads
    int e = beg;
    if (nq > 0) {
        int4 s = *(const int4*)(slots + e);          // aligned (beg % 64 == 0)
        for (int q = 0; q < nq; q++) {
            int4 snext;
            if (q + 1 < nq) snext = *(const int4*)(slots + e + 4);  // prefetch
            uint4 v0 = *(const uint4*)(hs + (size_t)s.x * F + sub * 8);
            uint4 v1 = *(const uint4*)(hs + (size_t)s.y * F + sub * 8);
            uint4 v2 = *(const uint4*)(hs + (size_t)s.z * F + sub * 8);
            uint4 v3 = *(const uint4*)(hs + (size_t)s.w * F + sub * 8);
            hacc4(a0, v0); hacc4(a1, v1); hacc4(a2, v2); hacc4(a3, v3);
            s = snext;
            e += 4;
        }
    }
    for (int t = beg + (deg & ~3); t < beg + deg; t++) {
        int r0 = __ldg(slots + t);
        hacc4(a1, *(const uint4*)(hs + (size_t)r0 * F + sub * 8));
    }

    // fp32 final combine
    const float d = rsqrtf((float)deg + 1.0f);
    float4 bva = *(const float4*)(bias + sub * 8);
    float4 bvb = *(const float4*)(bias + sub * 8 + 4);
    float o[8];
#pragma unroll
    for (int j = 0; j < 4; j++) {
        float2 f0 = __half22float2(a0[j]);
        float2 f1 = __half22float2(a1[j]);
        float2 f2 = __half22float2(a2[j]);
        float2 f3 = __half22float2(a3[j]);
        o[2 * j]     = (f0.x + f1.x) + (f2.x + f3.x);
        o[2 * j + 1] = (f0.y + f1.y) + (f2.y + f3.y);
    }
#pragma unroll
    for (int j = 0; j < 8; j++) {
        float bj = (j < 4) ? ((const float*)&bva)[j] : ((const float*)&bvb)[j - 4];
        o[j] = o[j] * d + bj;
        if (RELU) o[j] = fmaxf(o[j], 0.f);
    }

    if constexpr (sizeof(TOUT) == 2) {
        __half2 p[4];
#pragma unroll
        for (int j = 0; j < 4; j++) p[j] = __floats2half2_rn(o[2 * j], o[2 * j + 1]);
        *(uint4*)((__half*)out + (size_t)node * F + sub * 8) = *(uint4*)p;
    } else {
        float* op = (float*)out + (size_t)node * F + sub * 8;
        *(float4*)(op)     = make_float4(o[0], o[1], o[2], o[3]);
        *(float4*)(op + 4) = make_float4(o[4], o[5], o[6], o[7]);
    }
}

// ---------------------------------------------------------------------------
// Launch: R13 structure — side stream only for memset+fill (overlaps wconv);
// join before GEMM1 (its epilogue reads cnt). Sequential otherwise.
// ---------------------------------------------------------------------------
extern "C" void kernel_launch(void* const* d_in, const int* in_sizes, int n_in,
                              void* d_out, int out_size) {
    const float* x  = (const float*)d_in[0];
    const int*   ei = (const int*)d_in[1];
    const float* W1 = (const float*)d_in[2];
    const float* b1 = (const float*)d_in[3];
    const float* W2 = (const float*)d_in[4];
    const float* b2 = (const float*)d_in[5];
    float* out = (float*)d_out;

    const int* row = ei;
    const int* col = ei + EE;

    constexpr int SMEM1 = (64 * 136 + 128 * 136) * 2;  // 52,224 B (F=128)
    constexpr int SMEM2 = (64 * 136 + 128 * 72) * 2;   // 35,840 B (F=64)

    static __half *p_hs1 = nullptr, *p_hh = nullptr, *p_hs2 = nullptr,
                  *p_w1h = nullptr, *p_w2h = nullptr;
    static int *p_cnt = nullptr, *p_slots = nullptr;
    static cudaStream_t s_side = nullptr;
    static cudaEvent_t s_fork = nullptr, s_join = nullptr;
    if (!p_hs1) {
        cudaGetSymbolAddress((void**)&p_hs1,   g_hs1);
        cudaGetSymbolAddress((void**)&p_hh,    g_hh);
        cudaGetSymbolAddress((void**)&p_hs2,   g_hs2);
        cudaGetSymbolAddress((void**)&p_cnt,   g_cnt);
        cudaGetSymbolAddress((void**)&p_slots, g_slots);
        cudaGetSymbolAddress((void**)&p_w1h,   g_w1h);
        cudaGetSymbolAddress((void**)&p_w2h,   g_w2h);
        cudaFuncSetAttribute((const void*)gemm_tc_kernel<128, float>,
                             cudaFuncAttributeMaxDynamicSharedMemorySize, SMEM1);
        cudaFuncSetAttribute((const void*)gemm_tc_kernel<64, __half>,
                             cudaFuncAttributeMaxDynamicSharedMemorySize, SMEM2);
        cudaStreamCreateWithFlags(&s_side, cudaStreamNonBlocking);
        cudaEventCreateWithFlags(&s_fork, cudaEventDisableTiming);
        cudaEventCreateWithFlags(&s_join, cudaEventDisableTiming);
    }

    const int GBLK = (NN + 63) / 64;       // 782

    // ---- fork: CSR build on side stream (overlaps only wconv) ----
    cudaEventRecord(s_fork, 0);
    cudaStreamWaitEvent(s_side, s_fork, 0);
    cudaMemsetAsync(p_cnt, 0, (size_t)NN * sizeof(int), s_side);
    fill_direct_kernel<<<(EE / 2 + 255) / 256, 256, 0, s_side>>>(row, col, p_cnt, p_slots, EE);
    cudaEventRecord(s_join, s_side);

    // ---- main: W conversion ----
    {
        constexpr int NPAIR = (FIN * FHID + FHID * FOUT) / 2;
        wconv_kernel<<<(NPAIR + 255) / 256, 256>>>(W1, W2, p_w1h, p_w2h);
    }
    // gemm1 epilogue reads cnt — join here
    cudaStreamWaitEvent(0, s_join, 0);
    gemm_tc_kernel<128, float><<<GBLK, 256, SMEM1>>>(x, p_w1h, p_hs1, p_cnt, NN);

    // ---- layer 1 aggregate -> h (fp16) ----
    {
        long long threads = (long long)NN * (FHID / 8);
        aggregate_kernel<128, true, __half><<<(int)((threads + 255) / 256), 256>>>(
            p_hs1, p_slots, p_cnt, b1, p_hh, NN);
    }

    // ---- layer 2: fp16 tensor GEMM ----
    gemm_tc_kernel<64, __half><<<GBLK, 256, SMEM2>>>(p_hh, p_w2h, p_hs2, p_cnt, NN);

    // ---- layer 2 aggregate -> d_out (fp32) ----
    {
        long long threads = (long long)NN * (FOUT / 8);
        aggregate_kernel<64, false, float><<<(int)((threads + 255) / 256), 256>>>(
            p_hs2, p_slots, p_cnt, b2, out, NN);
    }
}

// round 16
// speedup vs baseline: 1.1983x; 1.0081x over previous
#include <cuda_runtime.h>
#include <cuda_bf16.h>
#include <cuda_fp16.h>
#include <cstdint>

// Problem constants
#define NN   50000
#define EE   800000
#define FIN  128
#define FHID 128
#define FOUT 64
#define SLOTS 64   // max in-degree slots per node (Poisson(16): P(deg>=64) ~ 1e-20)

// ---------------------------------------------------------------------------
// Scratch (static __device__ arrays — zero-initialized at module load).
// hs1/hs2 have ONE EXTRA ROW (index NN) that is never written: a permanent
// zero row used as the gather target for sentinel-padded quad slots.
// ---------------------------------------------------------------------------
__device__ __half g_hs1[(size_t)(NN + 1) * FHID];  // GEMM1 out (+ zero row)
__device__ __half g_hh[(size_t)NN * FHID];         // h = relu(dis*sum + b1)
__device__ __half g_hs2[(size_t)(NN + 1) * FOUT];  // GEMM2 out (+ zero row)
__device__ int    g_cnt[NN];                       // per-node edge count
__device__ int    g_slots[(size_t)NN * SLOTS];     // direct-mapped CSR
__device__ __half g_w1h[FIN * FHID];
__device__ __half g_w2h[FHID * FOUT];

// ---------------------------------------------------------------------------
// PTX helpers
// ---------------------------------------------------------------------------
__device__ __forceinline__ uint32_t smem_u32(const void* p) {
    return (uint32_t)__cvta_generic_to_shared(p);
}

__device__ __forceinline__ void ldmat_x4(uint32_t& r0, uint32_t& r1, uint32_t& r2, uint32_t& r3,
                                         uint32_t addr) {
    asm volatile("ldmatrix.sync.aligned.m8n8.x4.shared.b16 {%0,%1,%2,%3}, [%4];"
                 : "=r"(r0), "=r"(r1), "=r"(r2), "=r"(r3) : "r"(addr));
}
__device__ __forceinline__ void ldmat_x4_t(uint32_t& r0, uint32_t& r1, uint32_t& r2, uint32_t& r3,
                                           uint32_t addr) {
    asm volatile("ldmatrix.sync.aligned.m8n8.x4.trans.shared.b16 {%0,%1,%2,%3}, [%4];"
                 : "=r"(r0), "=r"(r1), "=r"(r2), "=r"(r3) : "r"(addr));
}

__device__ __forceinline__ void mma_f16(float* d, const uint32_t* a, uint32_t b0, uint32_t b1) {
    asm volatile(
        "mma.sync.aligned.m16n8k16.row.col.f32.f16.f16.f32 "
        "{%0,%1,%2,%3}, {%4,%5,%6,%7}, {%8,%9}, {%0,%1,%2,%3};"
        : "+f"(d[0]), "+f"(d[1]), "+f"(d[2]), "+f"(d[3])
        : "r"(a[0]), "r"(a[1]), "r"(a[2]), "r"(a[3]), "r"(b0), "r"(b1));
}

// fp16x2 accumulate of one uint4 (8 halves) into 4 half2 accumulators
__device__ __forceinline__ void hacc4(__half2* a, uint4 raw) {
    const __half2* h = (const __half2*)&raw;
    a[0] = __hadd2(a[0], h[0]);
    a[1] = __hadd2(a[1], h[1]);
    a[2] = __hadd2(a[2], h[2]);
    a[3] = __hadd2(a[3], h[3]);
}

// ---------------------------------------------------------------------------
// One-shot W conversion fp32 -> fp16
// ---------------------------------------------------------------------------
__global__ void wconv_kernel(const float* __restrict__ W1, const float* __restrict__ W2,
                             __half* __restrict__ w1h, __half* __restrict__ w2h) {
    constexpr int N1 = (FIN * FHID) / 2;
    constexpr int N2 = (FHID * FOUT) / 2;
    int i = blockIdx.x * blockDim.x + threadIdx.x;
    if (i < N1) {
        float2 v = *(const float2*)(W1 + (size_t)i * 2);
        *(__half2*)(w1h + (size_t)i * 2) = __floats2half2_rn(v.x, v.y);
    } else if (i < N1 + N2) {
        int j = i - N1;
        float2 v = *(const float2*)(W2 + (size_t)j * 2);
        *(__half2*)(w2h + (size_t)j * 2) = __floats2half2_rn(v.x, v.y);
    }
}

// ---------------------------------------------------------------------------
// Single-pass CSR build, 2 edges/thread
// ---------------------------------------------------------------------------
__global__ void fill_direct_kernel(const int* __restrict__ row, const int* __restrict__ col,
                                   int* __restrict__ cnt, int* __restrict__ slots, int e) {
    int i = blockIdx.x * blockDim.x + threadIdx.x;
    int j = i * 2;
    if (j + 1 < e) {
        int2 c = *(const int2*)(col + j);
        int2 r = *(const int2*)(row + j);
        int s0 = atomicAdd(&cnt[c.x], 1);
        int s1 = atomicAdd(&cnt[c.y], 1);
        slots[(size_t)c.x * SLOTS + s0] = r.x;
        slots[(size_t)c.y * SLOTS + s1] = r.y;
    } else if (j < e) {
        int c = col[j];
        int s = atomicAdd(&cnt[c], 1);
        slots[(size_t)c * SLOTS + s] = row[j];
    }
}

// ---------------------------------------------------------------------------
// Tensor-core GEMM, fp16 inputs, FULL K (=128) resident in smem (1 barrier):
//   out[N, F] = (x[N, 128] @ W[128, F]) * rsqrt(cnt[row]+1),  out fp16.
// BM=64, 8 warps (warp = 16-row slab x F/2 cols).
// ---------------------------------------------------------------------------
template <int F, typename TIN>
__global__ void __launch_bounds__(256)
gemm_tc_kernel(const TIN* __restrict__ x,
               const __half* __restrict__ wg,
               __half* __restrict__ out, const int* __restrict__ cnt, int nrows) {
    constexpr int BM   = 64;
    constexpr int KT   = 128;
    constexpr int NT   = F / 16;
    constexpr int ASTR = KT + 8;
    constexpr int WSTR = F + 8;

    extern __shared__ __half smem[];
    __half* Ah = smem;
    __half* Wh = Ah + BM * ASTR;

    const int tid  = threadIdx.x;
    const int lane = tid & 31;
    const int w    = tid >> 5;
    const int slab = w >> 1;
    const int ch   = w & 1;
    const int row0 = blockIdx.x * BM;

    float acc[NT][4];
#pragma unroll
    for (int nt = 0; nt < NT; nt++)
#pragma unroll
        for (int j = 0; j < 4; j++) acc[nt][j] = 0.f;

    const int mat  = lane >> 3;
    const int mrow = lane & 7;

    if constexpr (sizeof(TIN) == 4) {
        constexpr int NV = (BM * KT) / 4;
#pragma unroll
        for (int p = tid; p < NV; p += 256) {
            int r  = p / (KT / 4);
            int kq = (p % (KT / 4)) * 4;
            float4 v;
            int grow = row0 + r;
            if (grow < nrows)
                v = *(const float4*)((const float*)x + (size_t)grow * FIN + kq);
            else
                v = make_float4(0.f, 0.f, 0.f, 0.f);
            *(__half2*)(Ah + r * ASTR + kq)     = __floats2half2_rn(v.x, v.y);
            *(__half2*)(Ah + r * ASTR + kq + 2) = __floats2half2_rn(v.z, v.w);
        }
    } else {
        constexpr int NV = (BM * KT) / 8;
#pragma unroll
        for (int p = tid; p < NV; p += 256) {
            int r  = p / (KT / 8);
            int kq = (p % (KT / 8)) * 8;
            uint4 v;
            int grow = row0 + r;
            if (grow < nrows)
                v = *(const uint4*)((const __half*)x + (size_t)grow * FIN + kq);
            else
                v = make_uint4(0, 0, 0, 0);
            *(uint4*)(Ah + r * ASTR + kq) = v;
        }
    }
    {
        constexpr int NV = (KT * F) / 8;
#pragma unroll
        for (int p = tid; p < NV; p += 256) {
            int k = p / (F / 8);
            int c = (p % (F / 8)) * 8;
            *(uint4*)(Wh + k * WSTR + c) = *(const uint4*)(wg + (size_t)k * F + c);
        }
    }
    __syncthreads();

#pragma unroll
    for (int ks = 0; ks < KT / 16; ks++) {
        uint32_t ah[4];
        {
            int arow = slab * 16 + (mat & 1) * 8 + mrow;
            int acol = ks * 16 + (mat >> 1) * 8;
            ldmat_x4(ah[0], ah[1], ah[2], ah[3], smem_u32(Ah + arow * ASTR + acol));
        }
#pragma unroll
        for (int nt2 = 0; nt2 < NT / 2; nt2++) {
            int krow = ks * 16 + (mat & 1) * 8 + mrow;
            int ncol = ch * (F / 2) + nt2 * 16 + (mat >> 1) * 8;
            uint32_t bh[4];
            ldmat_x4_t(bh[0], bh[1], bh[2], bh[3], smem_u32(Wh + krow * WSTR + ncol));
            mma_f16(acc[2 * nt2],     ah, bh[0], bh[1]);
            mma_f16(acc[2 * nt2 + 1], ah, bh[2], bh[3]);
        }
    }

    {
        int r0 = row0 + slab * 16 + (lane >> 2);
        int r1 = r0 + 8;
        float s0 = (r0 < nrows) ? rsqrtf((float)__ldg(cnt + r0) + 1.0f) : 0.f;
        float s1 = (r1 < nrows) ? rsqrtf((float)__ldg(cnt + r1) + 1.0f) : 0.f;
        int cbase = ch * (F / 2) + (lane & 3) * 2;
#pragma unroll
        for (int nt = 0; nt < NT; nt++) {
            int c = cbase + nt * 8;
            if (r0 < nrows)
                *(__half2*)(out + (size_t)r0 * F + c) = __floats2half2_rn(acc[nt][0] * s0, acc[nt][1] * s0);
            if (r1 < nrows)
                *(__half2*)(out + (size_t)r1 * F + c) = __floats2half2_rn(acc[nt][2] * s1, acc[nt][3] * s1);
        }
    }
}

// ---------------------------------------------------------------------------
// Segment-sum aggregate over fp16 features; HADD2 accumulation, 4-way ILP,
// UNIFORM int4 quads: the last quad clamps out-of-range slots to the
// sentinel zero row (index n), eliminating the serial scalar tail.
// __launch_bounds__(256, 5) pushes occupancy from 4 to 5 CTAs/SM.
// ---------------------------------------------------------------------------
template <int F, bool RELU, typename TOUT>
__global__ void __launch_bounds__(256, 5)
aggregate_kernel(const __half* __restrict__ hs,
                 const int* __restrict__ slots, const int* __restrict__ cnt,
                 const float* __restrict__ bias,
                 TOUT* __restrict__ out, int n) {
    constexpr int LPN = F / 8;
    const int gtid = blockIdx.x * blockDim.x + threadIdx.x;
    const int node = gtid / LPN;
    const int sub  = gtid % LPN;
    if (node >= n) return;

    const int deg = __ldg(cnt + node);
    const int beg = node * SLOTS;

    __half2 a0[4], a1[4], a2[4], a3[4];
    // self loop seeds a0; others zero
    {
        uint4 s = *(const uint4*)(hs + (size_t)node * F + sub * 8);
        const __half2* h = (const __half2*)&s;
        __half2 z = __floats2half2_rn(0.f, 0.f);
#pragma unroll
        for (int j = 0; j < 4; j++) { a0[j] = h[j]; a1[j] = z; a2[j] = z; a3[j] = z; }
    }

    const int nq = (deg + 3) >> 2;     // sentinel-padded quads
    for (int q = 0; q < nq; q++) {
        int4 s = *(const int4*)(slots + beg + q * 4);   // aligned (beg % 64 == 0)
        int p = q * 4;
        int r0 = s.x;                          // p < deg always inside loop
        int r1 = (p + 1 < deg) ? s.y : n;      // n = zero sentinel row
        int r2 = (p + 2 < deg) ? s.z : n;
        int r3 = (p + 3 < deg) ? s.w : n;
        uint4 v0 = *(const uint4*)(hs + (size_t)r0 * F + sub * 8);
        uint4 v1 = *(const uint4*)(hs + (size_t)r1 * F + sub * 8);
        uint4 v2 = *(const uint4*)(hs + (size_t)r2 * F + sub * 8);
        uint4 v3 = *(const uint4*)(hs + (size_t)r3 * F + sub * 8);
        hacc4(a0, v0); hacc4(a1, v1); hacc4(a2, v2); hacc4(a3, v3);
    }

    // fp32 final combine
    const float d = rsqrtf((float)deg + 1.0f);
    float4 bva = *(const float4*)(bias + sub * 8);
    float4 bvb = *(const float4*)(bias + sub * 8 + 4);
    float o[8];
#pragma unroll
    for (int j = 0; j < 4; j++) {
        float2 f0 = __half22float2(a0[j]);
        float2 f1 = __half22float2(a1[j]);
        float2 f2 = __half22float2(a2[j]);
        float2 f3 = __half22float2(a3[j]);
        o[2 * j]     = (f0.x + f1.x) + (f2.x + f3.x);
        o[2 * j + 1] = (f0.y + f1.y) + (f2.y + f3.y);
    }
#pragma unroll
    for (int j = 0; j < 8; j++) {
        float bj = (j < 4) ? ((const float*)&bva)[j] : ((const float*)&bvb)[j - 4];
        o[j] = o[j] * d + bj;
        if (RELU) o[j] = fmaxf(o[j], 0.f);
    }

    if constexpr (sizeof(TOUT) == 2) {
        __half2 p[4];
#pragma unroll
        for (int j = 0; j < 4; j++) p[j] = __floats2half2_rn(o[2 * j], o[2 * j + 1]);
        *(uint4*)((__half*)out + (size_t)node * F + sub * 8) = *(uint4*)p;
    } else {
        float* op = (float*)out + (size_t)node * F + sub * 8;
        *(float4*)(op)     = make_float4(o[0], o[1], o[2], o[3]);
        *(float4*)(op + 4) = make_float4(o[4], o[5], o[6], o[7]);
    }
}

// ---------------------------------------------------------------------------
// Launch: side stream only for memset+fill (overlaps wconv); join before
// GEMM1 (its epilogue reads cnt). Sequential otherwise.
// ---------------------------------------------------------------------------
extern "C" void kernel_launch(void* const* d_in, const int* in_sizes, int n_in,
                              void* d_out, int out_size) {
    const float* x  = (const float*)d_in[0];
    const int*   ei = (const int*)d_in[1];
    const float* W1 = (const float*)d_in[2];
    const float* b1 = (const float*)d_in[3];
    const float* W2 = (const float*)d_in[4];
    const float* b2 = (const float*)d_in[5];
    float* out = (float*)d_out;

    const int* row = ei;
    const int* col = ei + EE;

    constexpr int SMEM1 = (64 * 136 + 128 * 136) * 2;  // 52,224 B (F=128)
    constexpr int SMEM2 = (64 * 136 + 128 * 72) * 2;   // 35,840 B (F=64)

    static __half *p_hs1 = nullptr, *p_hh = nullptr, *p_hs2 = nullptr,
                  *p_w1h = nullptr, *p_w2h = nullptr;
    static int *p_cnt = nullptr, *p_slots = nullptr;
    static cudaStream_t s_side = nullptr;
    static cudaEvent_t s_fork = nullptr, s_join = nullptr;
    if (!p_hs1) {
        cudaGetSymbolAddress((void**)&p_hs1,   g_hs1);
        cudaGetSymbolAddress((void**)&p_hh,    g_hh);
        cudaGetSymbolAddress((void**)&p_hs2,   g_hs2);
        cudaGetSymbolAddress((void**)&p_cnt,   g_cnt);
        cudaGetSymbolAddress((void**)&p_slots, g_slots);
        cudaGetSymbolAddress((void**)&p_w1h,   g_w1h);
        cudaGetSymbolAddress((void**)&p_w2h,   g_w2h);
        cudaFuncSetAttribute((const void*)gemm_tc_kernel<128, float>,
                             cudaFuncAttributeMaxDynamicSharedMemorySize, SMEM1);
        cudaFuncSetAttribute((const void*)gemm_tc_kernel<64, __half>,
                             cudaFuncAttributeMaxDynamicSharedMemorySize, SMEM2);
        cudaStreamCreateWithFlags(&s_side, cudaStreamNonBlocking);
        cudaEventCreateWithFlags(&s_fork, cudaEventDisableTiming);
        cudaEventCreateWithFlags(&s_join, cudaEventDisableTiming);
    }

    const int GBLK = (NN + 63) / 64;       // 782

    // ---- fork: CSR build on side stream (overlaps wconv) ----
    cudaEventRecord(s_fork, 0);
    cudaStreamWaitEvent(s_side, s_fork, 0);
    cudaMemsetAsync(p_cnt, 0, (size_t)NN * sizeof(int), s_side);
    fill_direct_kernel<<<(EE / 2 + 255) / 256, 256, 0, s_side>>>(row, col, p_cnt, p_slots, EE);
    cudaEventRecord(s_join, s_side);

    // ---- main: W conversion ----
    {
        constexpr int NPAIR = (FIN * FHID + FHID * FOUT) / 2;
        wconv_kernel<<<(NPAIR + 255) / 256, 256>>>(W1, W2, p_w1h, p_w2h);
    }
    // gemm1 epilogue reads cnt — join here
    cudaStreamWaitEvent(0, s_join, 0);
    gemm_tc_kernel<128, float><<<GBLK, 256, SMEM1>>>(x, p_w1h, p_hs1, p_cnt, NN);

    // ---- layer 1 aggregate -> h (fp16) ----
    {
        long long threads = (long long)NN * (FHID / 8);
        aggregate_kernel<128, true, __half><<<(int)((threads + 255) / 256), 256>>>(
            p_hs1, p_slots, p_cnt, b1, p_hh, NN);
    }

    // ---- layer 2: fp16 tensor GEMM ----
    gemm_tc_kernel<64, __half><<<GBLK, 256, SMEM2>>>(p_hh, p_w2h, p_hs2, p_cnt, NN);

    // ---- layer 2 aggregate -> d_out (fp32) ----
    {
        long long threads = (long long)NN * (FOUT / 8);
        aggregate_kernel<64, false, float><<<(int)((threads + 255) / 256), 256>>>(
            p_hs2, p_slots, p_cnt, b2, out, NN);
    }
}